// round 15
// baseline (speedup 1.0000x reference)
#include <cuda_runtime.h>
#include <cuda_fp16.h>
#include <cstdint>
#include <math.h>

#define SEQ   2048
#define HDIM  4096
#define NH    32
#define NKV   8
#define HD    128
#define IDIM  11008

// ---------------- fp32 scratch ----------------
__device__ float g_x   [(size_t)SEQ * HDIM];
__device__ float g_q   [(size_t)SEQ * NH * HD];
__device__ float g_k   [(size_t)SEQ * NKV * HD];
__device__ float g_v   [(size_t)SEQ * NKV * HD];
__device__ float g_sc  [(size_t)NH * SEQ * SEQ];
__device__ float g_attn[(size_t)SEQ * NH * HD];
__device__ float g_x2  [(size_t)SEQ * HDIM];
__device__ float g_gate[(size_t)SEQ * IDIM];
__device__ float g_up  [(size_t)SEQ * IDIM];

// ---------------- fp16 hi/lo split buffers ----------------
__device__ __half g_xeh[(size_t)SEQ*HDIM],      g_xel[(size_t)SEQ*HDIM];
__device__ __half g_xhh[(size_t)SEQ*HDIM],      g_xhl[(size_t)SEQ*HDIM];
__device__ __half g_fwh[(size_t)HDIM*2*HDIM],   g_fwl[(size_t)HDIM*2*HDIM];
__device__ __half g_hh [(size_t)SEQ*HDIM],      g_hl [(size_t)SEQ*HDIM];
__device__ __half g_qwh[(size_t)NH*HD*HDIM],    g_qwl[(size_t)NH*HD*HDIM];
__device__ __half g_kwh[(size_t)NKV*HD*HDIM],   g_kwl[(size_t)NKV*HD*HDIM];
__device__ __half g_vwh[(size_t)NKV*HD*HDIM],   g_vwl[(size_t)NKV*HD*HDIM];
__device__ __half g_owh[(size_t)HDIM*NH*HD],    g_owl[(size_t)HDIM*NH*HD];
__device__ __half g_qh [(size_t)SEQ*NH*HD],     g_ql [(size_t)SEQ*NH*HD];
__device__ __half g_kh [(size_t)SEQ*NKV*HD],    g_kl [(size_t)SEQ*NKV*HD];
__device__ __half g_vth[(size_t)NKV*HD*SEQ],    g_vtl[(size_t)NKV*HD*SEQ];
__device__ __half g_ph [(size_t)NH*SEQ*SEQ],    g_pl [(size_t)NH*SEQ*SEQ];
__device__ __half g_ath[(size_t)SEQ*NH*HD],     g_atl[(size_t)SEQ*NH*HD];
__device__ __half g_gwh[(size_t)IDIM*HDIM],     g_gwl[(size_t)IDIM*HDIM];
__device__ __half g_uwh[(size_t)IDIM*HDIM],     g_uwl[(size_t)IDIM*HDIM];
__device__ __half g_dwh[(size_t)HDIM*IDIM],     g_dwl[(size_t)HDIM*IDIM];
__device__ __half g_gh [(size_t)SEQ*IDIM],      g_gl [(size_t)SEQ*IDIM];

// ---------------- PTX helpers (sm_80-compatible only) ----------------
__device__ __forceinline__ uint32_t smem_to_u32(const void* p) {
    uint32_t a;
    asm("{ .reg .u64 t; cvta.to.shared.u64 t, %1; cvt.u32.u64 %0, t; }"
        : "=r"(a) : "l"(p));
    return a;
}

#define LDM4(r, addr) asm volatile( \
    "ldmatrix.sync.aligned.m8n8.x4.shared.b16 {%0,%1,%2,%3}, [%4];" \
    : "=r"((r)[0]), "=r"((r)[1]), "=r"((r)[2]), "=r"((r)[3]) : "r"(addr))

#define MMA(d, a, b0, b1) asm volatile( \
    "mma.sync.aligned.m16n8k16.row.col.f32.f16.f16.f32 " \
    "{%0,%1,%2,%3}, {%4,%5,%6,%7}, {%8,%9}, {%0,%1,%2,%3};" \
    : "+f"((d)[0]), "+f"((d)[1]), "+f"((d)[2]), "+f"((d)[3]) \
    : "r"((a)[0]), "r"((a)[1]), "r"((a)[2]), "r"((a)[3]), "r"(b0), "r"(b1))

#define CP16(dst, src) asm volatile( \
    "cp.async.cg.shared.global [%0], [%1], 16;" :: "r"(dst), "l"(src))

// ================= fp16xN tensor-core GEMM =================
// C = A*B^T with A = Ah+Al, B = Bh+Bl (fp16 hi/lo splits of fp32 values).
// npass==3: Ah*Bh + Ah*Bl + Al*Bh.  npass==2: Ah*Bh + Ah*Bl (Al unused/unloaded).
// R4-proven 2-stage cp.async pipeline.
// Optional: also emit hi/lo fp16 of C (Choh/Chol) to skip a split pass.
#define SMEM_STAGE 40960
#define OFF_AL 10240
#define OFF_BH 20480
#define OFF_BL 30720

__global__ void __launch_bounds__(256)
hgemm(const __half* __restrict__ Ah, const __half* __restrict__ Al, int lda, long sA, int adiv,
      const __half* __restrict__ Bh, const __half* __restrict__ Bl, int ldb, long sB, int bdiv,
      float* __restrict__ C, int ldc, long sC, int K,
      const float* __restrict__ bias, const float* __restrict__ resid, int causal,
      int npass, __half* __restrict__ Choh, __half* __restrict__ Chol)
{
    const int m0 = blockIdx.y * 128;
    const int n0 = blockIdx.x * 128;
    if (causal == 1 && n0 > m0) return;
    int Keff = K;
    if (causal == 2) { Keff = m0 + 128; if (Keff > K) Keff = K; }

    const int bz = blockIdx.z;
    const long aoff = (long)(bz / adiv) * sA;
    const long boff = (long)(bz / bdiv) * sB;
    Ah += aoff; Al += aoff;
    Bh += boff; Bl += boff;
    C += (long)bz * sC;
    if (resid) resid += (long)bz * sC;
    if (Choh) { Choh += (long)bz * sC; Chol += (long)bz * sC; }

    extern __shared__ char smem[];
    const uint32_t sbase = smem_to_u32(smem);

    const int tid  = threadIdx.x;
    const int lane = tid & 31;
    const int wid  = tid >> 5;
    const int wm   = wid >> 2;    // 0..1 : 64-row slab
    const int wn   = wid & 3;     // 0..3 : 32-col slab

    float acc[4][4][4];
#pragma unroll
    for (int i = 0; i < 4; i++)
#pragma unroll
        for (int j = 0; j < 4; j++)
#pragma unroll
            for (int c = 0; c < 4; c++) acc[i][j][c] = 0.f;

    const int T = Keff >> 5;

    const int r0a = tid >> 2;
    const int kc0 = (tid & 3) << 3;

#define LOADSTAGE(s, t) do {                                                   \
    uint32_t sb_ = sbase + (s) * SMEM_STAGE;                                   \
    int k0_ = (t) << 5;                                                        \
    _Pragma("unroll")                                                          \
    for (int j_ = 0; j_ < 2; j_++) {                                           \
        int row_ = r0a + (j_ << 6);                                            \
        uint32_t d_ = sb_ + (uint32_t)(row_ * 80 + (kc0 << 1));                \
        CP16(d_,          Ah + (long)(m0 + row_) * lda + k0_ + kc0);           \
        if (npass == 3)                                                        \
            CP16(d_ + OFF_AL, Al + (long)(m0 + row_) * lda + k0_ + kc0);       \
        CP16(d_ + OFF_BH, Bh + (long)(n0 + row_) * ldb + k0_ + kc0);           \
        CP16(d_ + OFF_BL, Bl + (long)(n0 + row_) * ldb + k0_ + kc0);           \
    }                                                                          \
    asm volatile("cp.async.commit_group;" ::: "memory");                       \
} while (0)

    LOADSTAGE(0, 0);
    if (T > 1) LOADSTAGE(1, 1);

    for (int t = 0; t < T; t++) {
        if (t + 1 < T) asm volatile("cp.async.wait_group 1;" ::: "memory");
        else           asm volatile("cp.async.wait_group 0;" ::: "memory");
        __syncthreads();

        const uint32_t sb = sbase + (t & 1) * SMEM_STAGE;
#pragma unroll
        for (int kk = 0; kk < 2; kk++) {
            uint32_t ahf[4][4], alf[4][4], bhf[2][4], blf[2][4];
            const uint32_t kb = (uint32_t)(((kk << 4) + ((lane >> 4) << 3)) << 1);
#pragma unroll
            for (int mt = 0; mt < 4; mt++) {
                uint32_t ad = sb + (uint32_t)((wm * 64 + mt * 16 + (lane & 15)) * 80) + kb;
                LDM4(ahf[mt], ad);
                if (npass == 3) LDM4(alf[mt], ad + OFF_AL);
            }
#pragma unroll
            for (int np = 0; np < 2; np++) {
                uint32_t bd = sb + OFF_BH +
                    (uint32_t)((wn * 32 + np * 16 + (lane & 7) + (((lane >> 3) & 1) << 3)) * 80) + kb;
                LDM4(bhf[np], bd);
                LDM4(blf[np], bd + (OFF_BL - OFF_BH));
            }
#pragma unroll
            for (int mt = 0; mt < 4; mt++) {
#pragma unroll
                for (int nt = 0; nt < 4; nt++) {
                    const int np = nt >> 1;
                    const int sel = nt & 1;
                    uint32_t b0 = bhf[np][sel], b1 = bhf[np][sel + 2];
                    uint32_t l0 = blf[np][sel], l1 = blf[np][sel + 2];
                    MMA(acc[mt][nt], ahf[mt], b0, b1);
                    MMA(acc[mt][nt], ahf[mt], l0, l1);
                    if (npass == 3) MMA(acc[mt][nt], alf[mt], b0, b1);
                }
            }
        }
        __syncthreads();
        if (t + 2 < T) LOADSTAGE(t & 1, t + 2);
    }
#undef LOADSTAGE

    // epilogue: c-frag lane mapping of m16n8k16
#pragma unroll
    for (int mt = 0; mt < 4; mt++) {
        const int r = m0 + wm * 64 + mt * 16 + (lane >> 2);
#pragma unroll
        for (int nt = 0; nt < 4; nt++) {
            const int cc = n0 + wn * 32 + nt * 8 + ((lane & 3) << 1);
            float2 v0 = make_float2(acc[mt][nt][0], acc[mt][nt][1]);
            float2 v1 = make_float2(acc[mt][nt][2], acc[mt][nt][3]);
            if (bias) {
                float2 b = *(const float2*)(bias + cc);
                v0.x += b.x; v0.y += b.y; v1.x += b.x; v1.y += b.y;
            }
            if (resid) {
                float2 q0 = *(const float2*)(resid + (long)r * ldc + cc);
                float2 q1 = *(const float2*)(resid + (long)(r + 8) * ldc + cc);
                v0.x += q0.x; v0.y += q0.y; v1.x += q1.x; v1.y += q1.y;
            }
            *(float2*)(C + (long)r * ldc + cc)       = v0;
            *(float2*)(C + (long)(r + 8) * ldc + cc) = v1;
            if (Choh) {
                __half h0x = __float2half(v0.x), h0y = __float2half(v0.y);
                __half h1x = __float2half(v1.x), h1y = __float2half(v1.y);
                *(__half2*)(Choh + (long)r * ldc + cc) = __halves2half2(h0x, h0y);
                *(__half2*)(Chol + (long)r * ldc + cc) = __halves2half2(
                    __float2half(v0.x - __half2float(h0x)),
                    __float2half(v0.y - __half2float(h0y)));
                *(__half2*)(Choh + (long)(r + 8) * ldc + cc) = __halves2half2(h1x, h1y);
                *(__half2*)(Chol + (long)(r + 8) * ldc + cc) = __halves2half2(
                    __float2half(v1.x - __half2float(h1x)),
                    __float2half(v1.y - __half2float(h1y)));
            }
        }
    }
}

// ---------------- reductions ----------------
__device__ __forceinline__ float block_reduce(float v, bool do_max) {
    __shared__ float sh[33];
    int lane = threadIdx.x & 31, wid = threadIdx.x >> 5;
#pragma unroll
    for (int o = 16; o; o >>= 1) {
        float t = __shfl_xor_sync(0xffffffffu, v, o);
        v = do_max ? fmaxf(v, t) : (v + t);
    }
    if (lane == 0) sh[wid] = v;
    __syncthreads();
    int nw = blockDim.x >> 5;
    v = (threadIdx.x < nw) ? sh[threadIdx.x] : (do_max ? -3.4e38f : 0.f);
    if (wid == 0) {
#pragma unroll
        for (int o = 16; o; o >>= 1) {
            float t = __shfl_xor_sync(0xffffffffu, v, o);
            v = do_max ? fmaxf(v, t) : (v + t);
        }
        if (lane == 0) sh[32] = v;
    }
    __syncthreads();
    float r = sh[32];
    __syncthreads();
    return r;
}

__device__ __forceinline__ void split1(float v, __half* hi, __half* lo, long i) {
    __half h = __float2half(v);
    hi[i] = h;
    lo[i] = __float2half(v - __half2float(h));
}

// ---------------- fp32 -> hi/lo split, 8 elems/thread vectorized ----------------
__global__ void split_kernel(const float* __restrict__ s,
                             __half* __restrict__ hi, __half* __restrict__ lo, long n)
{
    long i = ((long)blockIdx.x * blockDim.x + threadIdx.x) * 8;
    if (i >= n) return;
    __half hbuf[8], lbuf[8];
#pragma unroll
    for (int j = 0; j < 2; j++) {
        float4 v = *(const float4*)(s + i + j * 4);
        __half h0 = __float2half(v.x), h1 = __float2half(v.y);
        __half h2 = __float2half(v.z), h3 = __float2half(v.w);
        hbuf[j*4+0] = h0; hbuf[j*4+1] = h1; hbuf[j*4+2] = h2; hbuf[j*4+3] = h3;
        lbuf[j*4+0] = __float2half(v.x - __half2float(h0));
        lbuf[j*4+1] = __float2half(v.y - __half2float(h1));
        lbuf[j*4+2] = __float2half(v.z - __half2float(h2));
        lbuf[j*4+3] = __float2half(v.w - __half2float(h3));
    }
    *(uint4*)(hi + i) = *(const uint4*)hbuf;
    *(uint4*)(lo + i) = *(const uint4*)lbuf;
}

// ---------------- RMSNorm -> hi/lo ----------------
__global__ void rmsnorm_kernel(const float* __restrict__ x,
                               const float* __restrict__ w,
                               __half* __restrict__ yh, __half* __restrict__ yl)
{
    const long s = blockIdx.x;
    const float* xr = x + s * HDIM;
    float ss = 0.f;
    for (int i = threadIdx.x; i < HDIM; i += blockDim.x) {
        float v = xr[i];
        ss += v * v;
    }
    float tot = block_reduce(ss, false);
    float inv = rsqrtf(tot / (float)HDIM + 1e-6f);
    for (int i = threadIdx.x; i < HDIM; i += blockDim.x)
        split1(xr[i] * inv * w[i], yh, yl, s * HDIM + i);
}

// ---------------- RoPE: fp32 in -> hi/lo out ----------------
__global__ void rope_kernel(const float* __restrict__ src,
                            __half* __restrict__ dh, __half* __restrict__ dl,
                            int nheads, const int* __restrict__ pos32)
{
    const int s = blockIdx.x, h = blockIdx.y, j = threadIdx.x;  // j 0..63
    bool is64 = (pos32[1] == 0 && pos32[2] == 1);
    long long pv = is64 ? ((const long long*)pos32)[s] : (long long)pos32[s];
    float t = (float)pv;
    float inv = powf(10000.0f, -((float)(2 * j) / 128.0f));
    float c = cosf(t * inv), sn = sinf(t * inv);
    long base = ((long)s * nheads + h) * HD;
    float a = src[base + j], b = src[base + j + 64];
    split1(a * c - b * sn, dh, dl, base + j);
    split1(b * c + a * sn, dh, dl, base + j + 64);
}

// ---------------- V transpose -> hi/lo: vt[h][d][s] ----------------
__global__ void transpose_v_kernel(const float* __restrict__ v,
                                   __half* __restrict__ vh, __half* __restrict__ vl)
{
    __shared__ float t[32][33];
    const int h = blockIdx.z;
    const int s0 = blockIdx.x * 32, d0 = blockIdx.y * 32;
    const int x = threadIdx.x, y = threadIdx.y;
    for (int i = y; i < 32; i += 8)
        t[i][x] = v[(long)(s0 + i) * (NKV * HD) + h * HD + d0 + x];
    __syncthreads();
    for (int i = y; i < 32; i += 8)
        split1(t[x][i], vh, vl, ((long)h * HD + d0 + i) * SEQ + s0 + x);
}

// ---------------- softmax: fp32 scores -> hi/lo probs ----------------
__global__ void softmax_kernel(const float* __restrict__ scores,
                               const float* __restrict__ am,
                               __half* __restrict__ ph, __half* __restrict__ pl)
{
    const int s = blockIdx.x, h = blockIdx.y;
    const long ro = ((long)h * SEQ + s) * SEQ;
    const float* row = scores + ro;
    const float scale = 0.088388347648318447f;  // 1/sqrt(128)
    const int lim = s + 1;

    float m = -3.4e38f;
    for (int t = threadIdx.x; t < lim; t += blockDim.x) {
        float v = row[t] * scale;
        if (am[t] <= 0.5f) v += -3.40282e38f;
        m = fmaxf(m, v);
    }
    m = block_reduce(m, true);

    float sum = 0.f;
    for (int t = threadIdx.x; t < lim; t += blockDim.x) {
        float v = row[t] * scale;
        if (am[t] <= 0.5f) v += -3.40282e38f;
        sum += __expf(v - m);
    }
    sum = block_reduce(sum, false);
    float invs = 1.0f / sum;

    for (int t = threadIdx.x; t < lim; t += blockDim.x) {
        float v = row[t] * scale;
        if (am[t] <= 0.5f) v += -3.40282e38f;
        split1(__expf(v - m) * invs, ph, pl, ro + t);
    }
    const int zend = ((s >> 7) + 1) << 7;
    for (int t = lim + threadIdx.x; t < zend; t += blockDim.x) {
        ph[ro + t] = __float2half(0.f);
        pl[ro + t] = __float2half(0.f);
    }
}

// ---------------- SiLU(gate)*up -> hi/lo ----------------
__global__ void silu_mul_kernel(const float* __restrict__ g, const float* __restrict__ u,
                                __half* __restrict__ gh, __half* __restrict__ gl, long n)
{
    long i = ((long)blockIdx.x * blockDim.x + threadIdx.x) * 2;
    if (i < n) {
        float2 gv = *(const float2*)(g + i);
        float2 uv = *(const float2*)(u + i);
        float a = gv.x / (1.f + __expf(-gv.x)) * uv.x;
        float b = gv.y / (1.f + __expf(-gv.y)) * uv.y;
        __half ha = __float2half(a), hb = __float2half(b);
        *(__half2*)(gh + i) = __halves2half2(ha, hb);
        *(__half2*)(gl + i) = __halves2half2(
            __float2half(a - __half2float(ha)),
            __float2half(b - __half2float(hb)));
    }
}

// ---------------- launch ----------------
#define SYM(p, g) cudaGetSymbolAddress((void**)&p, g)

extern "C" void kernel_launch(void* const* d_in, const int* in_sizes, int n_in,
                              void* d_out, int out_size)
{
    const float* hidden      = (const float*)d_in[0];
    const float* embeds      = (const float*)d_in[1];
    const float* amask       = (const float*)d_in[2];
    const float* fc_w        = (const float*)d_in[3];
    const float* fc_b        = (const float*)d_in[4];
    const float* in_norm_w   = (const float*)d_in[5];
    const float* q_w         = (const float*)d_in[6];
    const float* k_w         = (const float*)d_in[7];
    const float* v_w         = (const float*)d_in[8];
    const float* o_w         = (const float*)d_in[9];
    const float* post_norm_w = (const float*)d_in[10];
    const float* gate_w      = (const float*)d_in[11];
    const float* up_w        = (const float*)d_in[12];
    const float* down_w      = (const float*)d_in[13];
    const int*   pos         = (const int*)d_in[14];
    float* out = (float*)d_out;

    float *x, *q, *k, *v, *sc, *attn, *x2, *gate, *up;
    SYM(x, g_x); SYM(q, g_q); SYM(k, g_k); SYM(v, g_v); SYM(sc, g_sc);
    SYM(attn, g_attn); SYM(x2, g_x2); SYM(gate, g_gate); SYM(up, g_up);

    __half *xeh,*xel,*xhh,*xhl,*fwh,*fwl,*hh,*hl,*qwh,*qwl,*kwh,*kwl,*vwh,*vwl,
           *owh,*owl,*qh,*ql,*kh,*kl,*vth,*vtl,*ph,*pl,*ath,*atl,
           *gwh,*gwl,*uwh,*uwl,*dwh,*dwl,*gh,*gl;
    SYM(xeh,g_xeh); SYM(xel,g_xel); SYM(xhh,g_xhh); SYM(xhl,g_xhl);
    SYM(fwh,g_fwh); SYM(fwl,g_fwl); SYM(hh,g_hh);   SYM(hl,g_hl);
    SYM(qwh,g_qwh); SYM(qwl,g_qwl); SYM(kwh,g_kwh); SYM(kwl,g_kwl);
    SYM(vwh,g_vwh); SYM(vwl,g_vwl); SYM(owh,g_owh); SYM(owl,g_owl);
    SYM(qh,g_qh);   SYM(ql,g_ql);   SYM(kh,g_kh);   SYM(kl,g_kl);
    SYM(vth,g_vth); SYM(vtl,g_vtl); SYM(ph,g_ph);   SYM(pl,g_pl);
    SYM(ath,g_ath); SYM(atl,g_atl); SYM(gwh,g_gwh); SYM(gwl,g_gwl);
    SYM(uwh,g_uwh); SYM(uwl,g_uwl); SYM(dwh,g_dwh); SYM(dwl,g_dwl);
    SYM(gh,g_gh);   SYM(gl,g_gl);

    const int SMEM = 2 * SMEM_STAGE;
    cudaFuncSetAttribute(hgemm, cudaFuncAttributeMaxDynamicSharedMemorySize, SMEM);
    dim3 blk(256);

#define SPLIT(src, h_, l_, n) split_kernel<<<(int)(((long)(n)) / 2048), 256>>>(src, h_, l_, (long)(n))

    // operand splits (all sizes are multiples of 2048)
    SPLIT(embeds, xeh, xel, (long)SEQ*HDIM);
    SPLIT(hidden, xhh, xhl, (long)SEQ*HDIM);
    SPLIT(fc_w,   fwh, fwl, (long)HDIM*2*HDIM);
    SPLIT(q_w,    qwh, qwl, (long)NH*HD*HDIM);
    SPLIT(k_w,    kwh, kwl, (long)NKV*HD*HDIM);
    SPLIT(v_w,    vwh, vwl, (long)NKV*HD*HDIM);
    SPLIT(o_w,    owh, owl, (long)HDIM*NH*HD);
    SPLIT(gate_w, gwh, gwl, (long)IDIM*HDIM);
    SPLIT(up_w,   uwh, uwl, (long)IDIM*HDIM);
    SPLIT(down_w, dwh, dwl, (long)HDIM*IDIM);

    // 1) x = embeds @ fc_w[:, :H]^T + fc_b          (2-pass)
    hgemm<<<dim3(HDIM/128, SEQ/128, 1), blk, SMEM>>>(
        xeh, xel, HDIM, 0, 1, fwh, fwl, 2*HDIM, 0, 1,
        x, HDIM, 0, HDIM, fc_b, nullptr, 0, 2, nullptr, nullptr);
    // 2) x += hidden @ fc_w[:, H:]^T                (2-pass)
    hgemm<<<dim3(HDIM/128, SEQ/128, 1), blk, SMEM>>>(
        xhh, xhl, HDIM, 0, 1, fwh + HDIM, fwl + HDIM, 2*HDIM, 0, 1,
        x, HDIM, 0, HDIM, nullptr, x, 0, 2, nullptr, nullptr);

    // 3) h = rmsnorm(x) -> hi/lo
    rmsnorm_kernel<<<SEQ, 256>>>(x, in_norm_w, hh, hl);

    // 4) q/k projections (3-pass, logit-critical), v (2-pass)
    hgemm<<<dim3((NH*HD)/128, SEQ/128, 1), blk, SMEM>>>(
        hh, hl, HDIM, 0, 1, qwh, qwl, HDIM, 0, 1,
        q, NH*HD, 0, HDIM, nullptr, nullptr, 0, 3, nullptr, nullptr);
    hgemm<<<dim3((NKV*HD)/128, SEQ/128, 1), blk, SMEM>>>(
        hh, hl, HDIM, 0, 1, kwh, kwl, HDIM, 0, 1,
        k, NKV*HD, 0, HDIM, nullptr, nullptr, 0, 3, nullptr, nullptr);
    hgemm<<<dim3((NKV*HD)/128, SEQ/128, 1), blk, SMEM>>>(
        hh, hl, HDIM, 0, 1, vwh, vwl, HDIM, 0, 1,
        v, NKV*HD, 0, HDIM, nullptr, nullptr, 0, 2, nullptr, nullptr);

    // 5) RoPE -> hi/lo;  V transpose -> hi/lo
    rope_kernel<<<dim3(SEQ, NH),  64>>>(q, qh, ql, NH,  pos);
    rope_kernel<<<dim3(SEQ, NKV), 64>>>(k, kh, kl, NKV, pos);
    transpose_v_kernel<<<dim3(SEQ/32, HD/32, NKV), dim3(32, 8)>>>(v, vth, vtl);

    // 6) scores[h] = q_h @ k_{h/4}^T  (causal tile-skip, 3-pass)
    hgemm<<<dim3(SEQ/128, SEQ/128, NH), blk, SMEM>>>(
        qh, ql, NH*HD, 128, 1, kh, kl, NKV*HD, 128, 4,
        sc, SEQ, (long)SEQ*SEQ, HD, nullptr, nullptr, 1, 3, nullptr, nullptr);

    // 7) softmax -> hi/lo probs
    softmax_kernel<<<dim3(SEQ, NH), 256>>>(sc, amask, ph, pl);

    // 8) attn[h] = P_h @ vt_{h/4}^T  (K truncated; fused hi/lo out; 2-pass)
    hgemm<<<dim3(1, SEQ/128, NH), blk, SMEM>>>(
        ph, pl, SEQ, (long)SEQ*SEQ, 1, vth, vtl, SEQ, (long)HD*SEQ, 4,
        attn, NH*HD, 128, SEQ, nullptr, nullptr, 2, 2, ath, atl);

    // 9) x2 = x + attn @ o_w^T                       (2-pass)
    hgemm<<<dim3(HDIM/128, SEQ/128, 1), blk, SMEM>>>(
        ath, atl, NH*HD, 0, 1, owh, owl, NH*HD, 0, 1,
        x2, HDIM, 0, NH*HD, nullptr, x, 0, 2, nullptr, nullptr);

    // 10) h = rmsnorm(x2) -> hi/lo
    rmsnorm_kernel<<<SEQ, 256>>>(x2, post_norm_w, hh, hl);

    // 11) gate/up projections                        (2-pass)
    hgemm<<<dim3(IDIM/128, SEQ/128, 1), blk, SMEM>>>(
        hh, hl, HDIM, 0, 1, gwh, gwl, HDIM, 0, 1,
        gate, IDIM, 0, HDIM, nullptr, nullptr, 0, 2, nullptr, nullptr);
    hgemm<<<dim3(IDIM/128, SEQ/128, 1), blk, SMEM>>>(
        hh, hl, HDIM, 0, 1, uwh, uwl, HDIM, 0, 1,
        up, IDIM, 0, HDIM, nullptr, nullptr, 0, 2, nullptr, nullptr);

    // 12) silu(gate)*up -> hi/lo
    silu_mul_kernel<<<(int)(((long)SEQ*IDIM) / 512), 256>>>(
        gate, up, gh, gl, (long)SEQ*IDIM);

    // 13) out = x2 + gate @ down_w^T                 (2-pass)
    hgemm<<<dim3(HDIM/128, SEQ/128, 1), blk, SMEM>>>(
        gh, gl, IDIM, 0, 1, dwh, dwl, IDIM, 0, 1,
        out, HDIM, 0, IDIM, nullptr, x2, 0, 2, nullptr, nullptr);
}

// round 16
// speedup vs baseline: 1.0023x; 1.0023x over previous
#include <cuda_runtime.h>
#include <cuda_fp16.h>
#include <cstdint>
#include <math.h>

#define SEQ   2048
#define HDIM  4096
#define NH    32
#define NKV   8
#define HD    128
#define IDIM  11008

// ---------------- fp32 scratch ----------------
__device__ float g_x   [(size_t)SEQ * HDIM];
__device__ float g_q   [(size_t)SEQ * NH * HD];
__device__ float g_k   [(size_t)SEQ * NKV * HD];
__device__ float g_v   [(size_t)SEQ * NKV * HD];
__device__ float g_sc  [(size_t)NH * SEQ * SEQ];
__device__ float g_attn[(size_t)SEQ * NH * HD];
__device__ float g_x2  [(size_t)SEQ * HDIM];
__device__ float g_gate[(size_t)SEQ * IDIM];
__device__ float g_up  [(size_t)SEQ * IDIM];

// ---------------- fp16 hi/lo split buffers ----------------
__device__ __half g_xeh[(size_t)SEQ*HDIM],      g_xel[(size_t)SEQ*HDIM];
__device__ __half g_xhh[(size_t)SEQ*HDIM],      g_xhl[(size_t)SEQ*HDIM];
__device__ __half g_fwh[(size_t)HDIM*2*HDIM],   g_fwl[(size_t)HDIM*2*HDIM];
__device__ __half g_hh [(size_t)SEQ*HDIM],      g_hl [(size_t)SEQ*HDIM];
__device__ __half g_qwh[(size_t)NH*HD*HDIM],    g_qwl[(size_t)NH*HD*HDIM];
__device__ __half g_kwh[(size_t)NKV*HD*HDIM],   g_kwl[(size_t)NKV*HD*HDIM];
__device__ __half g_vwh[(size_t)NKV*HD*HDIM],   g_vwl[(size_t)NKV*HD*HDIM];
__device__ __half g_owh[(size_t)HDIM*NH*HD],    g_owl[(size_t)HDIM*NH*HD];
__device__ __half g_qh [(size_t)SEQ*NH*HD],     g_ql [(size_t)SEQ*NH*HD];
__device__ __half g_kh [(size_t)SEQ*NKV*HD],    g_kl [(size_t)SEQ*NKV*HD];
__device__ __half g_vth[(size_t)NKV*HD*SEQ],    g_vtl[(size_t)NKV*HD*SEQ];
__device__ __half g_ph [(size_t)NH*SEQ*SEQ],    g_pl [(size_t)NH*SEQ*SEQ];
__device__ __half g_ath[(size_t)SEQ*NH*HD],     g_atl[(size_t)SEQ*NH*HD];
__device__ __half g_gwh[(size_t)IDIM*HDIM],     g_gwl[(size_t)IDIM*HDIM];
__device__ __half g_uwh[(size_t)IDIM*HDIM],     g_uwl[(size_t)IDIM*HDIM];
__device__ __half g_dwh[(size_t)HDIM*IDIM],     g_dwl[(size_t)HDIM*IDIM];
__device__ __half g_gh [(size_t)SEQ*IDIM],      g_gl [(size_t)SEQ*IDIM];

// ---------------- PTX helpers (sm_80-compatible only) ----------------
__device__ __forceinline__ uint32_t smem_to_u32(const void* p) {
    uint32_t a;
    asm("{ .reg .u64 t; cvta.to.shared.u64 t, %1; cvt.u32.u64 %0, t; }"
        : "=r"(a) : "l"(p));
    return a;
}

#define LDM4(r, addr) asm volatile( \
    "ldmatrix.sync.aligned.m8n8.x4.shared.b16 {%0,%1,%2,%3}, [%4];" \
    : "=r"((r)[0]), "=r"((r)[1]), "=r"((r)[2]), "=r"((r)[3]) : "r"(addr))

#define MMA(d, a, b0, b1) asm volatile( \
    "mma.sync.aligned.m16n8k16.row.col.f32.f16.f16.f32 " \
    "{%0,%1,%2,%3}, {%4,%5,%6,%7}, {%8,%9}, {%0,%1,%2,%3};" \
    : "+f"((d)[0]), "+f"((d)[1]), "+f"((d)[2]), "+f"((d)[3]) \
    : "r"((a)[0]), "r"((a)[1]), "r"((a)[2]), "r"((a)[3]), "r"(b0), "r"(b1))

#define CP16(dst, src) asm volatile( \
    "cp.async.cg.shared.global [%0], [%1], 16;" :: "r"(dst), "l"(src))

// ================= fp16xN tensor-core GEMM =================
// C = A*B^T with A = Ah+Al, B = Bh+Bl (fp16 hi/lo splits of fp32 values).
// npass==3: Ah*Bh + Ah*Bl + Al*Bh.  npass==2: Ah*Bh + Ah*Bl (Al unused/unloaded).
// R4-proven 2-stage cp.async pipeline.
// Optional: also emit hi/lo fp16 of C (Choh/Chol) to skip a split pass.
#define SMEM_STAGE 40960
#define OFF_AL 10240
#define OFF_BH 20480
#define OFF_BL 30720

__global__ void __launch_bounds__(256)
hgemm(const __half* __restrict__ Ah, const __half* __restrict__ Al, int lda, long sA, int adiv,
      const __half* __restrict__ Bh, const __half* __restrict__ Bl, int ldb, long sB, int bdiv,
      float* __restrict__ C, int ldc, long sC, int K,
      const float* __restrict__ bias, const float* __restrict__ resid, int causal,
      int npass, __half* __restrict__ Choh, __half* __restrict__ Chol)
{
    const int m0 = blockIdx.y * 128;
    const int n0 = blockIdx.x * 128;
    if (causal == 1 && n0 > m0) return;
    int Keff = K;
    if (causal == 2) { Keff = m0 + 128; if (Keff > K) Keff = K; }

    const int bz = blockIdx.z;
    const long aoff = (long)(bz / adiv) * sA;
    const long boff = (long)(bz / bdiv) * sB;
    Ah += aoff; Al += aoff;
    Bh += boff; Bl += boff;
    C += (long)bz * sC;
    if (resid) resid += (long)bz * sC;
    if (Choh) { Choh += (long)bz * sC; Chol += (long)bz * sC; }

    extern __shared__ char smem[];
    const uint32_t sbase = smem_to_u32(smem);

    const int tid  = threadIdx.x;
    const int lane = tid & 31;
    const int wid  = tid >> 5;
    const int wm   = wid >> 2;    // 0..1 : 64-row slab
    const int wn   = wid & 3;     // 0..3 : 32-col slab

    float acc[4][4][4];
#pragma unroll
    for (int i = 0; i < 4; i++)
#pragma unroll
        for (int j = 0; j < 4; j++)
#pragma unroll
            for (int c = 0; c < 4; c++) acc[i][j][c] = 0.f;

    const int T = Keff >> 5;

    const int r0a = tid >> 2;
    const int kc0 = (tid & 3) << 3;

#define LOADSTAGE(s, t) do {                                                   \
    uint32_t sb_ = sbase + (s) * SMEM_STAGE;                                   \
    int k0_ = (t) << 5;                                                        \
    _Pragma("unroll")                                                          \
    for (int j_ = 0; j_ < 2; j_++) {                                           \
        int row_ = r0a + (j_ << 6);                                            \
        uint32_t d_ = sb_ + (uint32_t)(row_ * 80 + (kc0 << 1));                \
        CP16(d_,          Ah + (long)(m0 + row_) * lda + k0_ + kc0);           \
        if (npass == 3)                                                        \
            CP16(d_ + OFF_AL, Al + (long)(m0 + row_) * lda + k0_ + kc0);       \
        CP16(d_ + OFF_BH, Bh + (long)(n0 + row_) * ldb + k0_ + kc0);           \
        CP16(d_ + OFF_BL, Bl + (long)(n0 + row_) * ldb + k0_ + kc0);           \
    }                                                                          \
    asm volatile("cp.async.commit_group;" ::: "memory");                       \
} while (0)

    LOADSTAGE(0, 0);
    if (T > 1) LOADSTAGE(1, 1);

    for (int t = 0; t < T; t++) {
        if (t + 1 < T) asm volatile("cp.async.wait_group 1;" ::: "memory");
        else           asm volatile("cp.async.wait_group 0;" ::: "memory");
        __syncthreads();

        const uint32_t sb = sbase + (t & 1) * SMEM_STAGE;
#pragma unroll
        for (int kk = 0; kk < 2; kk++) {
            uint32_t ahf[4][4], alf[4][4], bhf[2][4], blf[2][4];
            const uint32_t kb = (uint32_t)(((kk << 4) + ((lane >> 4) << 3)) << 1);
#pragma unroll
            for (int mt = 0; mt < 4; mt++) {
                uint32_t ad = sb + (uint32_t)((wm * 64 + mt * 16 + (lane & 15)) * 80) + kb;
                LDM4(ahf[mt], ad);
                if (npass == 3) LDM4(alf[mt], ad + OFF_AL);
            }
#pragma unroll
            for (int np = 0; np < 2; np++) {
                uint32_t bd = sb + OFF_BH +
                    (uint32_t)((wn * 32 + np * 16 + (lane & 7) + (((lane >> 3) & 1) << 3)) * 80) + kb;
                LDM4(bhf[np], bd);
                LDM4(blf[np], bd + (OFF_BL - OFF_BH));
            }
#pragma unroll
            for (int mt = 0; mt < 4; mt++) {
#pragma unroll
                for (int nt = 0; nt < 4; nt++) {
                    const int np = nt >> 1;
                    const int sel = nt & 1;
                    uint32_t b0 = bhf[np][sel], b1 = bhf[np][sel + 2];
                    uint32_t l0 = blf[np][sel], l1 = blf[np][sel + 2];
                    MMA(acc[mt][nt], ahf[mt], b0, b1);
                    MMA(acc[mt][nt], ahf[mt], l0, l1);
                    if (npass == 3) MMA(acc[mt][nt], alf[mt], b0, b1);
                }
            }
        }
        __syncthreads();
        if (t + 2 < T) LOADSTAGE(t & 1, t + 2);
    }
#undef LOADSTAGE

    // epilogue: c-frag lane mapping of m16n8k16
#pragma unroll
    for (int mt = 0; mt < 4; mt++) {
        const int r = m0 + wm * 64 + mt * 16 + (lane >> 2);
#pragma unroll
        for (int nt = 0; nt < 4; nt++) {
            const int cc = n0 + wn * 32 + nt * 8 + ((lane & 3) << 1);
            float2 v0 = make_float2(acc[mt][nt][0], acc[mt][nt][1]);
            float2 v1 = make_float2(acc[mt][nt][2], acc[mt][nt][3]);
            if (bias) {
                float2 b = *(const float2*)(bias + cc);
                v0.x += b.x; v0.y += b.y; v1.x += b.x; v1.y += b.y;
            }
            if (resid) {
                float2 q0 = *(const float2*)(resid + (long)r * ldc + cc);
                float2 q1 = *(const float2*)(resid + (long)(r + 8) * ldc + cc);
                v0.x += q0.x; v0.y += q0.y; v1.x += q1.x; v1.y += q1.y;
            }
            *(float2*)(C + (long)r * ldc + cc)       = v0;
            *(float2*)(C + (long)(r + 8) * ldc + cc) = v1;
            if (Choh) {
                __half h0x = __float2half(v0.x), h0y = __float2half(v0.y);
                __half h1x = __float2half(v1.x), h1y = __float2half(v1.y);
                *(__half2*)(Choh + (long)r * ldc + cc) = __halves2half2(h0x, h0y);
                *(__half2*)(Chol + (long)r * ldc + cc) = __halves2half2(
                    __float2half(v0.x - __half2float(h0x)),
                    __float2half(v0.y - __half2float(h0y)));
                *(__half2*)(Choh + (long)(r + 8) * ldc + cc) = __halves2half2(h1x, h1y);
                *(__half2*)(Chol + (long)(r + 8) * ldc + cc) = __halves2half2(
                    __float2half(v1.x - __half2float(h1x)),
                    __float2half(v1.y - __half2float(h1y)));
            }
        }
    }
}

// ---------------- reductions ----------------
__device__ __forceinline__ float block_reduce(float v, bool do_max) {
    __shared__ float sh[33];
    int lane = threadIdx.x & 31, wid = threadIdx.x >> 5;
#pragma unroll
    for (int o = 16; o; o >>= 1) {
        float t = __shfl_xor_sync(0xffffffffu, v, o);
        v = do_max ? fmaxf(v, t) : (v + t);
    }
    if (lane == 0) sh[wid] = v;
    __syncthreads();
    int nw = blockDim.x >> 5;
    v = (threadIdx.x < nw) ? sh[threadIdx.x] : (do_max ? -3.4e38f : 0.f);
    if (wid == 0) {
#pragma unroll
        for (int o = 16; o; o >>= 1) {
            float t = __shfl_xor_sync(0xffffffffu, v, o);
            v = do_max ? fmaxf(v, t) : (v + t);
        }
        if (lane == 0) sh[32] = v;
    }
    __syncthreads();
    float r = sh[32];
    __syncthreads();
    return r;
}

__device__ __forceinline__ void split1(float v, __half* hi, __half* lo, long i) {
    __half h = __float2half(v);
    hi[i] = h;
    lo[i] = __float2half(v - __half2float(h));
}

// ---------------- fp32 -> hi/lo split, 8 elems/thread vectorized ----------------
__global__ void split_kernel(const float* __restrict__ s,
                             __half* __restrict__ hi, __half* __restrict__ lo, long n)
{
    long i = ((long)blockIdx.x * blockDim.x + threadIdx.x) * 8;
    if (i >= n) return;
    __half hbuf[8], lbuf[8];
#pragma unroll
    for (int j = 0; j < 2; j++) {
        float4 v = *(const float4*)(s + i + j * 4);
        __half h0 = __float2half(v.x), h1 = __float2half(v.y);
        __half h2 = __float2half(v.z), h3 = __float2half(v.w);
        hbuf[j*4+0] = h0; hbuf[j*4+1] = h1; hbuf[j*4+2] = h2; hbuf[j*4+3] = h3;
        lbuf[j*4+0] = __float2half(v.x - __half2float(h0));
        lbuf[j*4+1] = __float2half(v.y - __half2float(h1));
        lbuf[j*4+2] = __float2half(v.z - __half2float(h2));
        lbuf[j*4+3] = __float2half(v.w - __half2float(h3));
    }
    *(uint4*)(hi + i) = *(const uint4*)hbuf;
    *(uint4*)(lo + i) = *(const uint4*)lbuf;
}

// ---------------- RMSNorm -> hi/lo ----------------
__global__ void rmsnorm_kernel(const float* __restrict__ x,
                               const float* __restrict__ w,
                               __half* __restrict__ yh, __half* __restrict__ yl)
{
    const long s = blockIdx.x;
    const float* xr = x + s * HDIM;
    float ss = 0.f;
    for (int i = threadIdx.x; i < HDIM; i += blockDim.x) {
        float v = xr[i];
        ss += v * v;
    }
    float tot = block_reduce(ss, false);
    float inv = rsqrtf(tot / (float)HDIM + 1e-6f);
    for (int i = threadIdx.x; i < HDIM; i += blockDim.x)
        split1(xr[i] * inv * w[i], yh, yl, s * HDIM + i);
}

// ---------------- RoPE: fp32 in -> hi/lo out ----------------
__global__ void rope_kernel(const float* __restrict__ src,
                            __half* __restrict__ dh, __half* __restrict__ dl,
                            int nheads, const int* __restrict__ pos32)
{
    const int s = blockIdx.x, h = blockIdx.y, j = threadIdx.x;  // j 0..63
    bool is64 = (pos32[1] == 0 && pos32[2] == 1);
    long long pv = is64 ? ((const long long*)pos32)[s] : (long long)pos32[s];
    float t = (float)pv;
    float inv = powf(10000.0f, -((float)(2 * j) / 128.0f));
    float c = cosf(t * inv), sn = sinf(t * inv);
    long base = ((long)s * nheads + h) * HD;
    float a = src[base + j], b = src[base + j + 64];
    split1(a * c - b * sn, dh, dl, base + j);
    split1(b * c + a * sn, dh, dl, base + j + 64);
}

// ---------------- V transpose -> hi/lo: vt[h][d][s] ----------------
__global__ void transpose_v_kernel(const float* __restrict__ v,
                                   __half* __restrict__ vh, __half* __restrict__ vl)
{
    __shared__ float t[32][33];
    const int h = blockIdx.z;
    const int s0 = blockIdx.x * 32, d0 = blockIdx.y * 32;
    const int x = threadIdx.x, y = threadIdx.y;
    for (int i = y; i < 32; i += 8)
        t[i][x] = v[(long)(s0 + i) * (NKV * HD) + h * HD + d0 + x];
    __syncthreads();
    for (int i = y; i < 32; i += 8)
        split1(t[x][i], vh, vl, ((long)h * HD + d0 + i) * SEQ + s0 + x);
}

// ---------------- softmax: fp32 scores -> hi/lo probs ----------------
__global__ void softmax_kernel(const float* __restrict__ scores,
                               const float* __restrict__ am,
                               __half* __restrict__ ph, __half* __restrict__ pl)
{
    const int s = blockIdx.x, h = blockIdx.y;
    const long ro = ((long)h * SEQ + s) * SEQ;
    const float* row = scores + ro;
    const float scale = 0.088388347648318447f;  // 1/sqrt(128)
    const int lim = s + 1;

    float m = -3.4e38f;
    for (int t = threadIdx.x; t < lim; t += blockDim.x) {
        float v = row[t] * scale;
        if (am[t] <= 0.5f) v += -3.40282e38f;
        m = fmaxf(m, v);
    }
    m = block_reduce(m, true);

    float sum = 0.f;
    for (int t = threadIdx.x; t < lim; t += blockDim.x) {
        float v = row[t] * scale;
        if (am[t] <= 0.5f) v += -3.40282e38f;
        sum += __expf(v - m);
    }
    sum = block_reduce(sum, false);
    float invs = 1.0f / sum;

    for (int t = threadIdx.x; t < lim; t += blockDim.x) {
        float v = row[t] * scale;
        if (am[t] <= 0.5f) v += -3.40282e38f;
        split1(__expf(v - m) * invs, ph, pl, ro + t);
    }
    const int zend = ((s >> 7) + 1) << 7;
    for (int t = lim + threadIdx.x; t < zend; t += blockDim.x) {
        ph[ro + t] = __float2half(0.f);
        pl[ro + t] = __float2half(0.f);
    }
}

// ---------------- SiLU(gate)*up -> hi/lo ----------------
__global__ void silu_mul_kernel(const float* __restrict__ g, const float* __restrict__ u,
                                __half* __restrict__ gh, __half* __restrict__ gl, long n)
{
    long i = ((long)blockIdx.x * blockDim.x + threadIdx.x) * 2;
    if (i < n) {
        float2 gv = *(const float2*)(g + i);
        float2 uv = *(const float2*)(u + i);
        float a = gv.x / (1.f + __expf(-gv.x)) * uv.x;
        float b = gv.y / (1.f + __expf(-gv.y)) * uv.y;
        __half ha = __float2half(a), hb = __float2half(b);
        *(__half2*)(gh + i) = __halves2half2(ha, hb);
        *(__half2*)(gl + i) = __halves2half2(
            __float2half(a - __half2float(ha)),
            __float2half(b - __half2float(hb)));
    }
}

// ---------------- launch ----------------
#define SYM(p, g) cudaGetSymbolAddress((void**)&p, g)

extern "C" void kernel_launch(void* const* d_in, const int* in_sizes, int n_in,
                              void* d_out, int out_size)
{
    const float* hidden      = (const float*)d_in[0];
    const float* embeds      = (const float*)d_in[1];
    const float* amask       = (const float*)d_in[2];
    const float* fc_w        = (const float*)d_in[3];
    const float* fc_b        = (const float*)d_in[4];
    const float* in_norm_w   = (const float*)d_in[5];
    const float* q_w         = (const float*)d_in[6];
    const float* k_w         = (const float*)d_in[7];
    const float* v_w         = (const float*)d_in[8];
    const float* o_w         = (const float*)d_in[9];
    const float* post_norm_w = (const float*)d_in[10];
    const float* gate_w      = (const float*)d_in[11];
    const float* up_w        = (const float*)d_in[12];
    const float* down_w      = (const float*)d_in[13];
    const int*   pos         = (const int*)d_in[14];
    float* out = (float*)d_out;

    float *x, *q, *k, *v, *sc, *attn, *x2, *gate, *up;
    SYM(x, g_x); SYM(q, g_q); SYM(k, g_k); SYM(v, g_v); SYM(sc, g_sc);
    SYM(attn, g_attn); SYM(x2, g_x2); SYM(gate, g_gate); SYM(up, g_up);

    __half *xeh,*xel,*xhh,*xhl,*fwh,*fwl,*hh,*hl,*qwh,*qwl,*kwh,*kwl,*vwh,*vwl,
           *owh,*owl,*qh,*ql,*kh,*kl,*vth,*vtl,*ph,*pl,*ath,*atl,
           *gwh,*gwl,*uwh,*uwl,*dwh,*dwl,*gh,*gl;
    SYM(xeh,g_xeh); SYM(xel,g_xel); SYM(xhh,g_xhh); SYM(xhl,g_xhl);
    SYM(fwh,g_fwh); SYM(fwl,g_fwl); SYM(hh,g_hh);   SYM(hl,g_hl);
    SYM(qwh,g_qwh); SYM(qwl,g_qwl); SYM(kwh,g_kwh); SYM(kwl,g_kwl);
    SYM(vwh,g_vwh); SYM(vwl,g_vwl); SYM(owh,g_owh); SYM(owl,g_owl);
    SYM(qh,g_qh);   SYM(ql,g_ql);   SYM(kh,g_kh);   SYM(kl,g_kl);
    SYM(vth,g_vth); SYM(vtl,g_vtl); SYM(ph,g_ph);   SYM(pl,g_pl);
    SYM(ath,g_ath); SYM(atl,g_atl); SYM(gwh,g_gwh); SYM(gwl,g_gwl);
    SYM(uwh,g_uwh); SYM(uwl,g_uwl); SYM(dwh,g_dwh); SYM(dwl,g_dwl);
    SYM(gh,g_gh);   SYM(gl,g_gl);

    const int SMEM = 2 * SMEM_STAGE;
    cudaFuncSetAttribute(hgemm, cudaFuncAttributeMaxDynamicSharedMemorySize, SMEM);
    dim3 blk(256);

#define SPLIT(src, h_, l_, n) split_kernel<<<(int)(((long)(n)) / 2048), 256>>>(src, h_, l_, (long)(n))

    // operand splits (all sizes are multiples of 2048)
    SPLIT(embeds, xeh, xel, (long)SEQ*HDIM);
    SPLIT(hidden, xhh, xhl, (long)SEQ*HDIM);
    SPLIT(fc_w,   fwh, fwl, (long)HDIM*2*HDIM);
    SPLIT(q_w,    qwh, qwl, (long)NH*HD*HDIM);
    SPLIT(k_w,    kwh, kwl, (long)NKV*HD*HDIM);
    SPLIT(v_w,    vwh, vwl, (long)NKV*HD*HDIM);
    SPLIT(o_w,    owh, owl, (long)HDIM*NH*HD);
    SPLIT(gate_w, gwh, gwl, (long)IDIM*HDIM);
    SPLIT(up_w,   uwh, uwl, (long)IDIM*HDIM);
    SPLIT(down_w, dwh, dwl, (long)HDIM*IDIM);

    // 1) x = embeds @ fc_w[:, :H]^T + fc_b          (2-pass)
    hgemm<<<dim3(HDIM/128, SEQ/128, 1), blk, SMEM>>>(
        xeh, xel, HDIM, 0, 1, fwh, fwl, 2*HDIM, 0, 1,
        x, HDIM, 0, HDIM, fc_b, nullptr, 0, 2, nullptr, nullptr);
    // 2) x += hidden @ fc_w[:, H:]^T                (2-pass)
    hgemm<<<dim3(HDIM/128, SEQ/128, 1), blk, SMEM>>>(
        xhh, xhl, HDIM, 0, 1, fwh + HDIM, fwl + HDIM, 2*HDIM, 0, 1,
        x, HDIM, 0, HDIM, nullptr, x, 0, 2, nullptr, nullptr);

    // 3) h = rmsnorm(x) -> hi/lo
    rmsnorm_kernel<<<SEQ, 256>>>(x, in_norm_w, hh, hl);

    // 4) q/k projections (3-pass, logit-critical), v (2-pass)
    hgemm<<<dim3((NH*HD)/128, SEQ/128, 1), blk, SMEM>>>(
        hh, hl, HDIM, 0, 1, qwh, qwl, HDIM, 0, 1,
        q, NH*HD, 0, HDIM, nullptr, nullptr, 0, 3, nullptr, nullptr);
    hgemm<<<dim3((NKV*HD)/128, SEQ/128, 1), blk, SMEM>>>(
        hh, hl, HDIM, 0, 1, kwh, kwl, HDIM, 0, 1,
        k, NKV*HD, 0, HDIM, nullptr, nullptr, 0, 3, nullptr, nullptr);
    hgemm<<<dim3((NKV*HD)/128, SEQ/128, 1), blk, SMEM>>>(
        hh, hl, HDIM, 0, 1, vwh, vwl, HDIM, 0, 1,
        v, NKV*HD, 0, HDIM, nullptr, nullptr, 0, 2, nullptr, nullptr);

    // 5) RoPE -> hi/lo;  V transpose -> hi/lo
    rope_kernel<<<dim3(SEQ, NH),  64>>>(q, qh, ql, NH,  pos);
    rope_kernel<<<dim3(SEQ, NKV), 64>>>(k, kh, kl, NKV, pos);
    transpose_v_kernel<<<dim3(SEQ/32, HD/32, NKV), dim3(32, 8)>>>(v, vth, vtl);

    // 6) scores[h] = q_h @ k_{h/4}^T  (causal tile-skip, 3-pass)
    hgemm<<<dim3(SEQ/128, SEQ/128, NH), blk, SMEM>>>(
        qh, ql, NH*HD, 128, 1, kh, kl, NKV*HD, 128, 4,
        sc, SEQ, (long)SEQ*SEQ, HD, nullptr, nullptr, 1, 3, nullptr, nullptr);

    // 7) softmax -> hi/lo probs
    softmax_kernel<<<dim3(SEQ, NH), 256>>>(sc, amask, ph, pl);

    // 8) attn[h] = P_h @ vt_{h/4}^T  (K truncated; fused hi/lo out; 2-pass)
    hgemm<<<dim3(1, SEQ/128, NH), blk, SMEM>>>(
        ph, pl, SEQ, (long)SEQ*SEQ, 1, vth, vtl, SEQ, (long)HD*SEQ, 4,
        attn, NH*HD, 128, SEQ, nullptr, nullptr, 2, 2, ath, atl);

    // 9) x2 = x + attn @ o_w^T                       (2-pass)
    hgemm<<<dim3(HDIM/128, SEQ/128, 1), blk, SMEM>>>(
        ath, atl, NH*HD, 0, 1, owh, owl, NH*HD, 0, 1,
        x2, HDIM, 0, NH*HD, nullptr, x, 0, 2, nullptr, nullptr);

    // 10) h = rmsnorm(x2) -> hi/lo
    rmsnorm_kernel<<<SEQ, 256>>>(x2, post_norm_w, hh, hl);

    // 11) gate/up projections                        (2-pass)
    hgemm<<<dim3(IDIM/128, SEQ/128, 1), blk, SMEM>>>(
        hh, hl, HDIM, 0, 1, gwh, gwl, HDIM, 0, 1,
        gate, IDIM, 0, HDIM, nullptr, nullptr, 0, 2, nullptr, nullptr);
    hgemm<<<dim3(IDIM/128, SEQ/128, 1), blk, SMEM>>>(
        hh, hl, HDIM, 0, 1, uwh, uwl, HDIM, 0, 1,
        up, IDIM, 0, HDIM, nullptr, nullptr, 0, 2, nullptr, nullptr);

    // 12) silu(gate)*up -> hi/lo
    silu_mul_kernel<<<(int)(((long)SEQ*IDIM) / 512), 256>>>(
        gate, up, gh, gl, (long)SEQ*IDIM);

    // 13) out = x2 + gate @ down_w^T                 (2-pass)
    hgemm<<<dim3(HDIM/128, SEQ/128, 1), blk, SMEM>>>(
        gh, gl, IDIM, 0, 1, dwh, dwl, IDIM, 0, 1,
        out, HDIM, 0, IDIM, nullptr, x2, 0, 2, nullptr, nullptr);
}